// round 3
// baseline (speedup 1.0000x reference)
#include <cuda_runtime.h>
#include <cooperative_groups.h>

namespace cg = cooperative_groups;

#define VOCABN 1000
#define EMBN   128
#define HIDN   256
#define G4N    1024   // 4*HID
#define BN     64
#define TN     1024

#define CL     8      // CTAs per cluster
#define GB     4      // batch rows per cluster
#define NTH    512    // 4 k-quarters x 128 gate rows

// Precomputed per-vocab gate projections: proj[v][g] = emb[v].W_ih[g] + b_ih[g] + b_hh[g]
__device__ float g_proj[VOCABN * G4N];

__device__ __forceinline__ unsigned long long fma2(unsigned long long a,
                                                   unsigned long long b,
                                                   unsigned long long c) {
    unsigned long long d;
    asm("fma.rn.f32x2 %0, %1, %2, %3;" : "=l"(d) : "l"(a), "l"(b), "l"(c));
    return d;
}
__device__ __forceinline__ unsigned long long add2(unsigned long long a,
                                                   unsigned long long b) {
    unsigned long long d;
    asm("add.rn.f32x2 %0, %1, %2;" : "=l"(d) : "l"(a), "l"(b));
    return d;
}
__device__ __forceinline__ float lo32(unsigned long long v) {
    return __uint_as_float((unsigned)v);
}
__device__ __forceinline__ float hi32(unsigned long long v) {
    return __uint_as_float((unsigned)(v >> 32));
}

__device__ __forceinline__ float sigf(float x) {
    return __fdividef(1.0f, 1.0f + __expf(-x));
}
__device__ __forceinline__ float tanhf_(float x) {
    return 1.0f - __fdividef(2.0f, __expf(2.0f * x) + 1.0f);
}

// ---------------------------------------------------------------------------
// Kernel 1: vocab projection table. 250 blocks x 256 threads, 4 vocab/block.
// ---------------------------------------------------------------------------
__global__ void __launch_bounds__(256) proj_kernel(
    const float* __restrict__ emb, const float* __restrict__ W_ih,
    const float* __restrict__ b_ih, const float* __restrict__ b_hh)
{
    __shared__ float4 es4[4][EMBN / 4];
    const int v0 = blockIdx.x * 4;
    const int tid = threadIdx.x;
    for (int i = tid; i < 4 * EMBN; i += 256) {
        int v = i >> 7, e = i & 127;
        ((float*)es4)[v * EMBN + e] = emb[(v0 + v) * EMBN + e];
    }
    __syncthreads();

    const float4* W4 = (const float4*)W_ih;
#pragma unroll
    for (int rr = 0; rr < 4; rr++) {
        int g = tid + rr * 256;
        float a0 = 0.f, a1 = 0.f, a2 = 0.f, a3 = 0.f;
#pragma unroll
        for (int e4 = 0; e4 < EMBN / 4; e4++) {
            float4 w  = W4[g * (EMBN / 4) + e4];
            float4 x0 = es4[0][e4];
            float4 x1 = es4[1][e4];
            float4 x2 = es4[2][e4];
            float4 x3 = es4[3][e4];
            a0 += w.x * x0.x + w.y * x0.y + w.z * x0.z + w.w * x0.w;
            a1 += w.x * x1.x + w.y * x1.y + w.z * x1.z + w.w * x1.w;
            a2 += w.x * x2.x + w.y * x2.y + w.z * x2.z + w.w * x2.w;
            a3 += w.x * x3.x + w.y * x3.y + w.z * x3.z + w.w * x3.w;
        }
        float bias = b_ih[g] + b_hh[g];
        g_proj[(v0 + 0) * G4N + g] = a0 + bias;
        g_proj[(v0 + 1) * G4N + g] = a1 + bias;
        g_proj[(v0 + 2) * G4N + g] = a2 + bias;
        g_proj[(v0 + 3) * G4N + g] = a3 + bias;
    }
}

// ---------------------------------------------------------------------------
// Kernel 2: recurrence. 16 clusters x 8 CTAs; each cluster owns 4 batch rows.
// CTA rank r owns h indices [r*32, r*32+32) => 128 W_hh gate rows, held in
// REGISTERS (64 floats / thread across 4 k-quarters). h is double-buffered in
// SMEM batch-major; matvec runs as packed f32x2 over adjacent k.
// ---------------------------------------------------------------------------
__global__ void __launch_bounds__(NTH, 1) __cluster_dims__(CL, 1, 1)
lstm_kernel(const int* __restrict__ tokens, const int* __restrict__ lengths,
            const float* __restrict__ W_hh, float* __restrict__ out)
{
    __shared__ float      hb[2][GB][HIDN];      // 8 KB, batch-major h
    __shared__ ulonglong2 psum[3][2][128];      // 12 KB, packed partials (q=1..3)
    __shared__ float      gsmT[GB][128];        // 2 KB, gate values batch-major

    cg::cluster_group cluster = cg::this_cluster();
    const int rank = blockIdx.x;               // 0..7
    const int cid  = blockIdx.y;               // 0..15
    const int tid  = threadIdx.x;
    const int lr   = tid & 127;                // gate row 0..127 (gate = lr>>5, h = lr&31)
    const int q    = tid >> 7;                 // k-quarter 0..3
    const int base = rank * 32;
    const int grow = (lr >> 5) * HIDN + base + (lr & 31);
    const int b0   = cid * GB;

    // --- W_hh slice into registers: 64 floats = 32 packed f32x2 pairs ---
    unsigned long long wpair[32];
    {
        const ulonglong2* wr =
            (const ulonglong2*)(W_hh + (size_t)grow * HIDN + q * 64);
#pragma unroll
        for (int j = 0; j < 16; j++) {
            ulonglong2 v = wr[j];
            wpair[2 * j]     = v.x;
            wpair[2 * j + 1] = v.y;
        }
    }

    // h buffer 0 = 0
    for (int i = tid; i < GB * HIDN; i += NTH) ((float*)hb[0])[i] = 0.f;

    const int len0 = lengths[b0 + 0];
    const int len1 = lengths[b0 + 1];
    const int len2 = lengths[b0 + 2];
    const int len3 = lengths[b0 + 3];
    int steps = max(max(len0, len1), max(len2, len3));
    if (steps > TN) steps = TN;

    // per-(h,batch) cell state for tid<128: hl = tid&31, b = tid>>5
    float creg = 0.f, hreg = 0.f;
    int mylen = 0;
    float xw0 = 0.f, xw1 = 0.f, xw2 = 0.f, xw3 = 0.f;
    if (tid < 128) {
        const int myb = tid >> 5;
        mylen = lengths[b0 + myb];
        xw0 = g_proj[tokens[(b0 + 0) * TN] * G4N + grow];
        xw1 = g_proj[tokens[(b0 + 1) * TN] * G4N + grow];
        xw2 = g_proj[tokens[(b0 + 2) * TN] * G4N + grow];
        xw3 = g_proj[tokens[(b0 + 3) * TN] * G4N + grow];
    }
    __syncthreads();

    for (int t = 0; t < steps; t++) {
        float xn0, xn1, xn2, xn3;
        if (tid < 128) {  // prefetch next step's input projection (L2 latency hidden)
            int tn = min(t + 1, TN - 1);
            xn0 = g_proj[tokens[(b0 + 0) * TN + tn] * G4N + grow];
            xn1 = g_proj[tokens[(b0 + 1) * TN + tn] * G4N + grow];
            xn2 = g_proj[tokens[(b0 + 2) * TN + tn] * G4N + grow];
            xn3 = g_proj[tokens[(b0 + 3) * TN + tn] * G4N + grow];
        }

        // --- packed matvec: this thread's gate row, k-quarter, 4 batches ---
        const float* h0p = hb[t & 1][0] + q * 64;
        const float* h1p = hb[t & 1][1] + q * 64;
        const float* h2p = hb[t & 1][2] + q * 64;
        const float* h3p = hb[t & 1][3] + q * 64;
        unsigned long long a0 = 0ull, a1 = 0ull, a2 = 0ull, a3 = 0ull;
#pragma unroll 4
        for (int c = 0; c < 16; c++) {
            ulonglong2 h0 = *(const ulonglong2*)(h0p + c * 4);
            ulonglong2 h1 = *(const ulonglong2*)(h1p + c * 4);
            ulonglong2 h2 = *(const ulonglong2*)(h2p + c * 4);
            ulonglong2 h3 = *(const ulonglong2*)(h3p + c * 4);
            a0 = fma2(wpair[2 * c], h0.x, a0);
            a1 = fma2(wpair[2 * c], h1.x, a1);
            a2 = fma2(wpair[2 * c], h2.x, a2);
            a3 = fma2(wpair[2 * c], h3.x, a3);
            a0 = fma2(wpair[2 * c + 1], h0.y, a0);
            a1 = fma2(wpair[2 * c + 1], h1.y, a1);
            a2 = fma2(wpair[2 * c + 1], h2.y, a2);
            a3 = fma2(wpair[2 * c + 1], h3.y, a3);
        }
        if (q) {
            psum[q - 1][0][lr] = make_ulonglong2(a0, a1);
            psum[q - 1][1][lr] = make_ulonglong2(a2, a3);
        }
        __syncthreads();

        if (tid < 128) {
            // reduce 4 k-quarters (still packed), add xw, unpack
            ulonglong2 p0 = psum[0][0][lr];
            ulonglong2 p1 = psum[1][0][lr];
            ulonglong2 p2 = psum[2][0][lr];
            a0 = add2(add2(a0, p0.x), add2(p1.x, p2.x));
            a1 = add2(add2(a1, p0.y), add2(p1.y, p2.y));
            p0 = psum[0][1][lr];
            p1 = psum[1][1][lr];
            p2 = psum[2][1][lr];
            a2 = add2(add2(a2, p0.x), add2(p1.x, p2.x));
            a3 = add2(add2(a3, p0.y), add2(p1.y, p2.y));
            gsmT[0][lr] = lo32(a0) + hi32(a0) + xw0;
            gsmT[1][lr] = lo32(a1) + hi32(a1) + xw1;
            gsmT[2][lr] = lo32(a2) + hi32(a2) + xw2;
            gsmT[3][lr] = lo32(a3) + hi32(a3) + xw3;
            xw0 = xn0; xw1 = xn1; xw2 = xn2; xw3 = xn3;
        }
        __syncthreads();

        if (tid < 128) {
            // cell update: one thread per (h index, batch)
            const int hl = tid & 31;
            const int b  = tid >> 5;
            float ig = gsmT[b][hl];
            float fg = gsmT[b][32 + hl];
            float gg = gsmT[b][64 + hl];
            float og = gsmT[b][96 + hl];
            float i_ = sigf(ig), f_ = sigf(fg), z_ = tanhf_(gg), o_ = sigf(og);
            float cn = f_ * creg + i_ * z_;
            float hn = o_ * tanhf_(cn);
            if (t < mylen) { creg = cn; hreg = hn; }
            // push (frozen-aware) h to every CTA's next buffer
            float* dst = &hb[(t & 1) ^ 1][b][base + hl];
#pragma unroll
            for (int r = 0; r < CL; r++) {
                float* p = cluster.map_shared_rank(dst, r);
                *p = hreg;
            }
        }
        cluster.sync();  // release my pushes, acquire peers' h_new
    }

    if (tid < 128) {
        const int hl = tid & 31;
        const int b  = tid >> 5;
        out[(b0 + b) * HIDN + base + hl] = hreg;
    }
}

// ---------------------------------------------------------------------------
extern "C" void kernel_launch(void* const* d_in, const int* in_sizes, int n_in,
                              void* d_out, int out_size)
{
    const int*   tokens  = (const int*)d_in[0];
    const int*   lengths = (const int*)d_in[1];
    const float* emb     = (const float*)d_in[2];
    const float* W_ih    = (const float*)d_in[3];
    const float* W_hh    = (const float*)d_in[4];
    const float* b_ih    = (const float*)d_in[5];
    const float* b_hh    = (const float*)d_in[6];
    float* out = (float*)d_out;

    proj_kernel<<<VOCABN / 4, 256>>>(emb, W_ih, b_ih, b_hh);

    dim3 grid(CL, BN / GB);
    lstm_kernel<<<grid, NTH>>>(tokens, lengths, W_hh, out);
}